// round 14
// baseline (speedup 1.0000x reference)
#include <cuda_runtime.h>
#include <cstdint>

// Chebyshev-KAN: out[b] = sum_d sum_{k=0..8} coeff[d*9+k] * T_k(x[b,d])
// x: (16384, 512) f32; coeff: (4608,) f32; out: (16384,) f32.
//
// R14: bytes-in-flight play. Warp = 64-dim slice (2 dims/lane, monomial
// coeffs in 9 packed-f32x2 regs). TILE=8 rows per group (2KB per warp-load),
// depth-2 register pipeline -> ~2KB/warp outstanding continuously; at
// 3 CTAs/SM (launch_bounds(256,3), ~70 regs) that's ~48KB/SM in flight,
// 3x the Little's-law requirement for full stream bandwidth. Grid 444
// (148x3, single wave), 5 grid-stride iterations, fused epilogue (smem
// partials, one __syncthreads, direct out stores). Single kernel.

#define DIM      512
#define NDEG     9
#define THREADS  256
#define TILE     8
#define NGROUPS  2048          // 16384 / 8
#define GRID1    444           // 148 SMs x 3 CTAs, single wave
#define MAXIT    5             // ceil(2048/444)
#define SSTRIDE  9

typedef unsigned long long ull;

__device__ __forceinline__ ull pack2(float lo, float hi) {
    ull r; asm("mov.b64 %0, {%1, %2};" : "=l"(r) : "f"(lo), "f"(hi)); return r;
}
__device__ __forceinline__ void unpack2(ull v, float& lo, float& hi) {
    asm("mov.b64 {%0, %1}, %2;" : "=f"(lo), "=f"(hi) : "l"(v));
}
__device__ __forceinline__ ull fma2(ull a, ull b, ull c) {
    ull r; asm("fma.rn.f32x2 %0, %1, %2, %3;" : "=l"(r) : "l"(a), "l"(b), "l"(c)); return r;
}

// Chebyshev coeffs c[0..8] -> monomial coeffs a[0..8].
__device__ __forceinline__ void cheb2mono(const float* __restrict__ c, float* a) {
    a[8] = 128.0f * c[8];
    a[7] =  64.0f * c[7];
    a[6] = fmaf(-256.0f, c[8], 32.0f * c[6]);
    a[5] = fmaf(-112.0f, c[7], 16.0f * c[5]);
    a[4] = fmaf(160.0f, c[8], fmaf(-48.0f, c[6], 8.0f * c[4]));
    a[3] = fmaf( 56.0f, c[7], fmaf(-20.0f, c[5], 4.0f * c[3]));
    a[2] = fmaf(-32.0f, c[8], fmaf(18.0f, c[6], fmaf(-8.0f, c[4], 2.0f * c[2])));
    a[1] = fmaf( -7.0f, c[7], fmaf( 5.0f, c[5], fmaf(-3.0f, c[3], c[1])));
    a[0] = ((c[0] - c[2]) + (c[4] - c[6])) + c[8];
}

__device__ __forceinline__ void load_group(const float2* __restrict__ x2,
                                           int g, int col2, float2* xb) {
    const float2* p = x2 + (size_t)(TILE * g) * (DIM / 2) + col2;
    #pragma unroll
    for (int r = 0; r < TILE; ++r)
        xb[r] = p[r * (DIM / 2)];
}

// Compute 8 rows of this warp's slice s, fold (16 shuffles), store partials.
__device__ __forceinline__ void do_group(const float2* xb, const ull* A,
                                         float* __restrict__ s_part,
                                         int s, int slot, int lane) {
    float acc[TILE];
    #pragma unroll
    for (int r = 0; r < TILE; ++r) {
        ull xp = pack2(xb[r].x, xb[r].y);
        ull p = A[8];
        #pragma unroll
        for (int k = 7; k >= 0; --k) p = fma2(p, xp, A[k]);
        float lo, hi; unpack2(p, lo, hi);
        acc[r] = lo + hi;
    }
    // fold tree: 8 rows -> 1 value per lane octant (16 shuffles).
    // row bits: bit0=(lane>>4)&1, bit1=(lane>>3)&1, bit2=(lane>>2)&1
    float v4[4];
    #pragma unroll
    for (int i = 0; i < 4; ++i) {
        float lo = acc[2*i]   + __shfl_xor_sync(0xffffffffu, acc[2*i],   16);
        float hi = acc[2*i+1] + __shfl_xor_sync(0xffffffffu, acc[2*i+1], 16);
        v4[i] = (lane & 16) ? hi : lo;
    }
    float v2[2];
    #pragma unroll
    for (int i = 0; i < 2; ++i) {
        float lo = v4[2*i]   + __shfl_xor_sync(0xffffffffu, v4[2*i],   8);
        float hi = v4[2*i+1] + __shfl_xor_sync(0xffffffffu, v4[2*i+1], 8);
        v2[i] = (lane & 8) ? hi : lo;
    }
    float u;
    {
        float lo = v2[0] + __shfl_xor_sync(0xffffffffu, v2[0], 4);
        float hi = v2[1] + __shfl_xor_sync(0xffffffffu, v2[1], 4);
        u = (lane & 4) ? hi : lo;
    }
    u += __shfl_xor_sync(0xffffffffu, u, 2);
    u += __shfl_xor_sync(0xffffffffu, u, 1);

    if ((lane & 3) == 0) {
        int rm = ((lane >> 4) & 1) | (((lane >> 3) & 1) << 1) | (((lane >> 2) & 1) << 2);
        s_part[(slot * TILE + rm) * SSTRIDE + s] = u;
    }
}

__global__ __launch_bounds__(THREADS, 3)
void kan_cheb_kernel(const float* __restrict__ x,
                     const float* __restrict__ coeff,
                     float* __restrict__ out)
{
    __shared__ float s_part[MAXIT * TILE * SSTRIDE];   // 5*8*9*4 = 1440 B

    const int tid  = threadIdx.x;
    const int lane = tid & 31;
    const int s    = tid >> 5;            // slice 0..7 (fixed per warp)
    const int d0   = s * 64 + lane * 2;
    const int col2 = d0 >> 1;
    const int bid  = blockIdx.x;

    const float2* x2 = reinterpret_cast<const float2*>(x);

    // issue first group's loads BEFORE coefficient work (independent)
    int g = bid;
    float2 xa[TILE], xb[TILE];
    load_group(x2, g, col2, xa);

    // coeff prologue: 18 consecutive floats -> monomial -> packed regs
    float cf[18];
    {
        const float2* c2 = reinterpret_cast<const float2*>(coeff + d0 * NDEG);
        #pragma unroll
        for (int i = 0; i < 9; ++i) { float2 v = c2[i]; cf[2*i] = v.x; cf[2*i+1] = v.y; }
    }
    ull A[9];
    {
        float t0[9], t1[9];
        cheb2mono(cf, t0); cheb2mono(cf + 9, t1);
        #pragma unroll
        for (int k = 0; k < 9; ++k) A[k] = pack2(t0[k], t1[k]);
    }

    // grid-stride loop, depth-2 register pipeline (2KB/warp outstanding)
    int slot = 0;
    for (;;) {
        int gn = g + GRID1;
        if (gn < NGROUPS) load_group(x2, gn, col2, xb);
        do_group(xa, A, s_part, s, slot, lane);
        g = gn; ++slot;
        if (g >= NGROUPS) break;

        gn = g + GRID1;
        if (gn < NGROUPS) load_group(x2, gn, col2, xa);
        do_group(xb, A, s_part, s, slot, lane);
        g = gn; ++slot;
        if (g >= NGROUPS) break;
    }

    // in-CTA finalize: one sync; thread (it,rm) sums 8 slice partials
    __syncthreads();
    if (tid < MAXIT * TILE) {
        const int it = tid >> 3;          // iteration slot
        const int rm = tid & 7;           // row within group
        const int gg = bid + it * GRID1;
        if (gg < NGROUPS) {
            const float* p = &s_part[tid * SSTRIDE];
            float r = ((p[0] + p[1]) + (p[2] + p[3])) + ((p[4] + p[5]) + (p[6] + p[7]));
            out[gg * TILE + rm] = r;
        }
    }
}

extern "C" void kernel_launch(void* const* d_in, const int* in_sizes, int n_in,
                              void* d_out, int out_size)
{
    const float* x     = (const float*)d_in[0];
    const float* coeff = (const float*)d_in[1];
    // d_in[2] = degree (int32, fixed at 8) — baked in at compile time.
    float* out = (float*)d_out;

    kan_cheb_kernel<<<GRID1, THREADS>>>(x, coeff, out);
}